// round 15
// baseline (speedup 1.0000x reference)
#include <cuda_runtime.h>
#include <cuda_fp16.h>
#include <cstdint>

// CliffordISTA — Round 13: operator precomposition. grad = X·Wc − Yb with
// Wc = Wf·Wb (fp16, built once via mma) and Yb = Y·Wb (fp32, built once).
// ONE gemm phase per iteration (was fwd+err+bwd), 2 dataflow waits per iter.

#define NDIM 512
#define MDIM 256
#define BDIM 64
#define NITER 50
#define STEPF 0.01f
#define KT 64
#define NTHREADS 512
#define GRID 128
#define SPLIT 4          // K splits of the per-iter gemm
#define NCT 32           // coltiles (64 realified cols each)
#define KX 2048          // X k-dim (realified n-space)
#define CG 2048          // G cols (realified n-space)
#define KMID 1024        // realified mid (m) space

#define BUF_BYTES 24576  // per stage: A 16K | B 8K
#define SMEM_TOTAL (2 * BUF_BYTES)

// ---------------- device globals ----------------
__device__ __half g_Wb[(size_t)CG * KMID];    // r(Wb^T): [2c2+ro][2j+ri]  4MB
__device__ __half g_WfT[(size_t)KX * KMID];   // r(Wf^T) k-major: [2c1+ri][2j+b] 4MB
__device__ __half g_Wc[(size_t)CG * KX];      // [colP=2c2+ro][kP=2c1+ri]  8MB
__device__ __half g_X[2][128 * KX];           // realified x, parity buffered
__device__ float g_xs[BDIM * NDIM * 8];       // blade state (CTA-private)
__device__ float g_yr[128 * KMID];            // realified y [row][2j+ri]
__device__ float g_Yb[128 * CG];              // Y·Wb (constant) fp32
__device__ float g_pg[2][(size_t)SPLIT * 128 * CG];   // G split partials 2x4MB
__device__ unsigned g_fg[NCT * 32];           // gemm done per coltile
__device__ unsigned g_fu[NCT * 32];           // upd done per coltile

// ---------------- helpers ----------------
__device__ __forceinline__ uint32_t smem_u32(const void* p) {
    uint32_t a;
    asm("{ .reg .u64 t; cvta.to.shared.u64 t, %1; cvt.u32.u64 %0, t; }" : "=r"(a) : "l"(p));
    return a;
}

#define CP_ASYNC16(smem, gptr) \
    asm volatile("cp.async.cg.shared.global [%0], [%1], 16;" :: "r"(smem), "l"(gptr))
#define CP_COMMIT() asm volatile("cp.async.commit_group;" ::: "memory")
#define CP_WAIT1()  asm volatile("cp.async.wait_group 1;" ::: "memory")
#define CP_WAIT0()  asm volatile("cp.async.wait_group 0;" ::: "memory")

__device__ __forceinline__ void ldsm4(uint32_t* r, uint32_t addr) {
    asm volatile("ldmatrix.sync.aligned.m8n8.x4.shared.b16 {%0,%1,%2,%3}, [%4];"
                 : "=r"(r[0]), "=r"(r[1]), "=r"(r[2]), "=r"(r[3]) : "r"(addr));
}

__device__ __forceinline__ void mma_fp16(float* c, const uint32_t* a, uint32_t b0, uint32_t b1) {
    asm volatile(
        "mma.sync.aligned.m16n8k16.row.col.f32.f16.f16.f32 "
        "{%0,%1,%2,%3}, {%4,%5,%6,%7}, {%8,%9}, {%0,%1,%2,%3};"
        : "+f"(c[0]), "+f"(c[1]), "+f"(c[2]), "+f"(c[3])
        : "r"(a[0]), "r"(a[1]), "r"(a[2]), "r"(a[3]), "r"(b0), "r"(b1));
}

// M(v)[q][p] for blade vector v[8]  (blades [1,e1,e2,e12,e3,e13,e23,e123])
__device__ __forceinline__ void pauli_entry(const float* v, int q, int p,
                                            float* re, float* im) {
    if (q == 0) {
        if (p == 0) { *re = v[0] + v[4]; *im = v[3] + v[7]; }
        else        { *re = v[1] - v[5]; *im = -v[2] + v[6]; }
    } else {
        if (p == 0) { *re = v[1] + v[5]; *im = v[2] + v[6]; }
        else        { *re = v[0] - v[4]; *im = -v[3] + v[7]; }
    }
}

__device__ __forceinline__ void flag_wait(const unsigned* f, unsigned tgt) {
    unsigned v;
    do {
        asm volatile("ld.volatile.global.u32 %0, [%1];" : "=r"(v) : "l"(f));
    } while ((int)(v - tgt) < 0);
}

// ---------------- build kernels ----------------
// g_Wb[col=4n+2q'+ro][k=4m+2p+ri] = realify of conj-transpose bwd op (R11 proven)
__global__ void build_wb(const float* __restrict__ A) {
    size_t idx = (size_t)blockIdx.x * blockDim.x + threadIdx.x;
    if (idx >= (size_t)CG * KMID) return;
    int col = (int)(idx >> 10), k = (int)(idx & (KMID - 1));
    int n = col >> 2, qp = (col >> 1) & 1, ro = col & 1;
    int m = k >> 2, p = (k >> 1) & 1, ri = k & 1;
    const float* a = A + ((size_t)m * NDIM + n) * 8;
    float re, im;
    pauli_entry(a, qp, p, &re, &im);
    float v = (ri == 0) ? (ro == 0 ? re : -im) : (ro == 0 ? im : re);
    g_Wb[idx] = __float2half(v);
}

// g_WfT[col=4n+2q+rc][k=4m+2p'+b] = r(Wf^T) transposed-storage (k-major)
__global__ void build_wfT(const float* __restrict__ A) {
    size_t idx = (size_t)blockIdx.x * blockDim.x + threadIdx.x;
    if (idx >= (size_t)KX * KMID) return;
    int col = (int)(idx >> 10), k = (int)(idx & (KMID - 1));
    int n = col >> 2, q = (col >> 1) & 1, rc = col & 1;
    int m = k >> 2, pp = (k >> 1) & 1, b = k & 1;
    const float* a = A + ((size_t)m * NDIM + n) * 8;
    float re, im;
    pauli_entry(a, q, pp, &re, &im);
    float v = (b == 0) ? (rc == 0 ? re : -im) : (rc == 0 ? im : re);
    g_WfT[idx] = __float2half(v);
}

__global__ void build_yr(const float* __restrict__ y) {
    int idx = blockIdx.x * blockDim.x + threadIdx.x;
    if (idx >= 128 * KMID) return;
    int row = idx >> 10, col = idx & (KMID - 1);
    int b = row >> 1, p = row & 1;
    int m = col >> 2, pp = (col >> 1) & 1, ro = col & 1;
    const float* yv = y + ((size_t)b * MDIM + m) * 8;
    float re, im;
    pauli_entry(yv, p, pp, &re, &im);
    g_yr[idx] = ro ? im : re;
}

// Yb[r][c] = sum_k yr[r][k] * Wb[c][k]  (fp32, one-time)
__global__ void build_yb() {
    int idx = blockIdx.x * blockDim.x + threadIdx.x;
    if (idx >= 128 * CG) return;
    int r = idx >> 11, c = idx & (CG - 1);
    const float2* yp = reinterpret_cast<const float2*>(g_yr + (size_t)r * KMID);
    const __half2* wp = reinterpret_cast<const __half2*>(g_Wb + (size_t)c * KMID);
    float acc = 0.0f;
    for (int k2 = 0; k2 < KMID / 2; k2++) {
        float2 a = yp[k2];
        float2 b = __half22float2(wp[k2]);
        acc += a.x * b.x + a.y * b.y;
    }
    g_Yb[idx] = acc;
}

__global__ void init_all() {
    int idx = blockIdx.x * blockDim.x + threadIdx.x;
    if (idx < BDIM * NDIM * 8) g_xs[idx] = 0.0f;
    if (idx < 128 * KX) {
        g_X[0][idx] = __float2half(0.0f);
        g_X[1][idx] = __float2half(0.0f);
    }
    if (idx < NCT * 32) { g_fg[idx] = 0u; g_fu[idx] = 0u; }
}

// ---------------- shared gemm pieces ----------------
// A 128 rows from Am, B 64 rows (c0-offset) from Wm, both k-major stride Kdim.
__device__ __forceinline__ void issue_stage(
    uint32_t sb, int buf, int tid, const __half* Am, const __half* Wm,
    int Kdim, int c0, int kk)
{
    uint32_t base = sb + buf * BUF_BYTES;
#pragma unroll
    for (int r = 0; r < 3; r++) {
        int q = tid + (r << 9);                // 1536 16B chunks per stage
        const __half* gp;
        uint32_t tb;
        int row, cc;
        if (q < 1024) {                        // A: 128 rows x 8 chunks
            row = q >> 3; cc = q & 7;
            gp = Am + (size_t)row * Kdim + kk + cc * 8;
            tb = base;
        } else {                               // B: 64 rows x 8 chunks
            int q2 = q - 1024;
            row = q2 >> 3; cc = q2 & 7;
            gp = Wm + (size_t)(c0 + row) * Kdim + kk + cc * 8;
            tb = base + 16384;
        }
        uint32_t off = (uint32_t)((row << 7) | ((cc ^ (row & 7)) << 4));
        CP_ASYNC16(tb + off, gp);
    }
    CP_COMMIT();
}

// Shared mainloop: accumulates into acc[2][2][4]; warp tile m32 x n16.
__device__ __forceinline__ void gemm_loop(
    uint32_t sb, const __half* Am, const __half* Wm, int Kdim, int c0,
    int k0, int nst, int wm, int wn, int lrow, int lhalf, int lsw, int tid,
    float acc[2][2][4])
{
    issue_stage(sb, 0, tid, Am, Wm, Kdim, c0, k0);
    for (int s = 0; s < nst; s++) {
        if (s + 1 < nst) {
            issue_stage(sb, (s + 1) & 1, tid, Am, Wm, Kdim, c0, k0 + (s + 1) * KT);
            CP_WAIT1();
        } else {
            CP_COMMIT();
            CP_WAIT0();
        }
        __syncthreads();
        uint32_t bufb = sb + (s & 1) * BUF_BYTES;
#pragma unroll
        for (int kk = 0; kk < 4; kk++) {
            uint32_t ksel = (uint32_t)((((kk << 1) | lhalf) ^ lsw) << 4);
            uint32_t ah[2][4], bb[4];
#pragma unroll
            for (int am = 0; am < 2; am++) {
                uint32_t rb = (uint32_t)((wm * 32 + am * 16 + lrow) << 7) + ksel;
                ldsm4(ah[am], bufb + rb);
            }
            {
                uint32_t rb = (uint32_t)((wn * 16 + lrow) << 7) + ksel;
                ldsm4(bb, bufb + 16384u + rb);
            }
#pragma unroll
            for (int am = 0; am < 2; am++)
#pragma unroll
                for (int sel = 0; sel < 2; sel++)
                    mma_fp16(acc[am][sel], ah[am], bb[sel], bb[sel + 2]);
        }
        __syncthreads();
    }
}

// ---------------- Wc build gemm: Wc = g_Wb(2048x1024) @ g_WfT^T ----------------
__global__ __launch_bounds__(NTHREADS, 1) void build_wc() {
    extern __shared__ char smem[];
    uint32_t sb = smem_u32(smem);
    const int tid = threadIdx.x;
    const int cb = blockIdx.x;     // 32 colblocks of 64
    const int rb = blockIdx.y;     // 16 rowblocks of 128
    const int warp = tid >> 5, lane = tid & 31;
    const int wm = warp >> 2, wn = warp & 3;
    const int lrow = lane & 15, lhalf = lane >> 4, lsw = lrow & 7;

    float acc[2][2][4];
#pragma unroll
    for (int am = 0; am < 2; am++)
#pragma unroll
        for (int sel = 0; sel < 2; sel++)
#pragma unroll
            for (int v = 0; v < 4; v++) acc[am][sel][v] = 0.0f;

    const __half* Am = g_Wb + (size_t)rb * 128 * KMID;
    gemm_loop(sb, Am, g_WfT, KMID, cb * 64, 0, KMID / KT,
              wm, wn, lrow, lhalf, lsw, tid, acc);

    const int qrow = lane >> 2, qcol2 = (lane & 3) << 1;
#pragma unroll
    for (int am = 0; am < 2; am++)
#pragma unroll
        for (int sel = 0; sel < 2; sel++) {
            int row = rb * 128 + wm * 32 + am * 16 + qrow;
            int col = cb * 64 + wn * 16 + sel * 8 + qcol2;
            *reinterpret_cast<__half2*>(&g_Wc[(size_t)row * KX + col]) =
                __floats2half2_rn(acc[am][sel][0], acc[am][sel][1]);
            *reinterpret_cast<__half2*>(&g_Wc[(size_t)(row + 8) * KX + col]) =
                __floats2half2_rn(acc[am][sel][2], acc[am][sel][3]);
        }
}

// ---------------- persistent kernel ----------------
__global__ __launch_bounds__(NTHREADS, 1) void ista_persist(float* __restrict__ out) {
    extern __shared__ char smem[];
    uint32_t sb = smem_u32(smem);
    const int cta = blockIdx.x;
    const int t = threadIdx.x;
    const int ct = cta >> 2;       // coltile (32)
    const int ks = cta & 3;        // K split (4)
    const int warp = t >> 5, lane = t & 31;
    const int wm = warp >> 2, wn = warp & 3;
    const int lrow = lane & 15, lhalf = lane >> 4, lsw = lrow & 7;
    const int qrow = lane >> 2, qcol2 = (lane & 3) << 1;

    for (int it = 0; it < NITER; it++) {
        const int p = it & 1;

        // ---- gemm: pg[p][ks] cols [ct*64,+64) = X[p] @ Wc-tile, K slice ks ----
        {
            float acc[2][2][4];
#pragma unroll
            for (int am = 0; am < 2; am++)
#pragma unroll
                for (int sel = 0; sel < 2; sel++)
#pragma unroll
                    for (int v = 0; v < 4; v++) acc[am][sel][v] = 0.0f;

            gemm_loop(sb, g_X[p], g_Wc, KX, ct * 64, ks * 512, 512 / KT,
                      wm, wn, lrow, lhalf, lsw, t, acc);

            float* po = g_pg[p] + (size_t)ks * 128 * CG;
#pragma unroll
            for (int am = 0; am < 2; am++)
#pragma unroll
                for (int sel = 0; sel < 2; sel++) {
                    int row = wm * 32 + am * 16 + qrow;
                    int col = ct * 64 + wn * 16 + sel * 8 + qcol2;
                    *reinterpret_cast<float2*>(&po[(size_t)row * CG + col]) =
                        make_float2(acc[am][sel][0], acc[am][sel][1]);
                    *reinterpret_cast<float2*>(&po[(size_t)(row + 8) * CG + col]) =
                        make_float2(acc[am][sel][2], acc[am][sel][3]);
                }
        }
        __syncthreads();
        if (t == 0) {
            __threadfence();
            atomicAdd(&g_fg[ct * 32], 1u);
            flag_wait(&g_fg[ct * 32], 4u * (it + 1));   // 4 splits of my coltile
            __threadfence();
        }
        __syncthreads();

        // ---- upd: b in [ks*16,+16), n in [ct*16,+16); G = sum(pg) - Yb ----
        if (t < 256) {
            int b = ks * 16 + (t >> 4);
            int n = ct * 16 + (t & 15);
            size_t r0 = (size_t)(2 * b) * CG + 4 * n;
            size_t r1 = r0 + CG;
            float4 yb0 = *reinterpret_cast<const float4*>(&g_Yb[r0]);
            float4 yb1 = *reinterpret_cast<const float4*>(&g_Yb[r1]);
            float4 G0 = make_float4(-yb0.x, -yb0.y, -yb0.z, -yb0.w);
            float4 G1 = make_float4(-yb1.x, -yb1.y, -yb1.z, -yb1.w);
#pragma unroll
            for (int q = 0; q < SPLIT; q++) {
                float4 a = *reinterpret_cast<const float4*>(
                    &g_pg[p][(size_t)q * 128 * CG + r0]);
                float4 c = *reinterpret_cast<const float4*>(
                    &g_pg[p][(size_t)q * 128 * CG + r1]);
                G0.x += a.x; G0.y += a.y; G0.z += a.z; G0.w += a.w;
                G1.x += c.x; G1.y += c.y; G1.z += c.z; G1.w += c.w;
            }
            float g[8];
            g[0] = 0.5f * (G0.x + G1.z);
            g[4] = 0.5f * (G0.x - G1.z);
            g[3] = 0.5f * (G0.y - G1.w);
            g[7] = 0.5f * (G0.y + G1.w);
            g[1] = 0.5f * (G0.z + G1.x);
            g[5] = 0.5f * (G1.x - G0.z);
            g[2] = 0.5f * (G1.y - G0.w);
            g[6] = 0.5f * (G0.w + G1.y);

            int idx = b * NDIM + n;
            float* xs = g_xs + (size_t)idx * 8;
            float x[8];
#pragma unroll
            for (int i = 0; i < 8; i++) {
                float xv = xs[i] - STEPF * g[i];
                float thr = (i == 0) ? 0.0f : ((i == 7) ? 0.002f : 0.001f);
                float a = fabsf(xv) - thr;
                x[i] = (a > 0.0f) ? copysignf(a, xv) : 0.0f;
                xs[i] = x[i];
            }
            const int p1 = (it + 1) & 1;
            __half2* X0 = reinterpret_cast<__half2*>(&g_X[p1][(size_t)(2 * b) * KX + 4 * n]);
            __half2* X1 = reinterpret_cast<__half2*>(&g_X[p1][(size_t)(2 * b + 1) * KX + 4 * n]);
            X0[0] = __floats2half2_rn(x[0] + x[4], x[3] + x[7]);
            X0[1] = __floats2half2_rn(x[1] - x[5], -x[2] + x[6]);
            X1[0] = __floats2half2_rn(x[1] + x[5], x[2] + x[6]);
            X1[1] = __floats2half2_rn(x[0] - x[4], -x[3] + x[7]);

            if (it == NITER - 1) {
                float4* po = reinterpret_cast<float4*>(&out[(size_t)idx * 8]);
                po[0] = make_float4(x[0], x[1], x[2], x[3]);
                po[1] = make_float4(x[4], x[5], x[6], x[7]);
            }
        }
        __syncthreads();
        if (t == 0) {
            __threadfence();
            atomicAdd(&g_fu[ct * 32], 1u);
            if (it + 1 < NITER) {
                unsigned tgt = 4u * (it + 1);
#pragma unroll
                for (int j = 0; j < 8; j++)          // X slice producers
                    flag_wait(&g_fu[(ks * 8 + j) * 32], tgt);
                flag_wait(&g_fu[ct * 32], tgt);      // pg WAR guard (own coltile)
                __threadfence();
            }
        }
        __syncthreads();
    }
}

// ---------------- host ----------------
extern "C" void kernel_launch(void* const* d_in, const int* in_sizes, int n_in,
                              void* d_out, int out_size)
{
    const float* y = (const float*)d_in[0];
    const float* A = (const float*)d_in[1];
    if (n_in >= 2 && in_sizes[0] > in_sizes[1]) {
        const float* t = y; y = A; A = t;
    }

    cudaFuncSetAttribute(build_wc, cudaFuncAttributeMaxDynamicSharedMemorySize, SMEM_TOTAL);
    cudaFuncSetAttribute(ista_persist, cudaFuncAttributeMaxDynamicSharedMemorySize, SMEM_TOTAL);

    build_wb<<<(int)(((size_t)CG * KMID + 255) / 256), 256>>>(A);
    build_wfT<<<(int)(((size_t)KX * KMID + 255) / 256), 256>>>(A);
    build_yr<<<(128 * KMID + 255) / 256, 256>>>(y);
    build_yb<<<(128 * CG + 255) / 256, 256>>>();
    build_wc<<<dim3(32, 16), NTHREADS, SMEM_TOTAL>>>();
    init_all<<<(128 * KX + 255) / 256, 256>>>();

    ista_persist<<<GRID, NTHREADS, SMEM_TOTAL>>>((float*)d_out);
}

// round 17
// speedup vs baseline: 1.7293x; 1.7293x over previous
#include <cuda_runtime.h>
#include <cuda_fp16.h>
#include <cstdint>

// CliffordISTA — Round 15 (resubmit of R14; previous round was an infra
// failure, kernel unmeasured): R13 operator precomposition (grad = X·Wc − Yb,
// ONE gemm phase/iter) with the 480us scalar build_yb replaced by an
// mma-based build (~4us). Persistent loop byte-identical to R13.

#define NDIM 512
#define MDIM 256
#define BDIM 64
#define NITER 50
#define STEPF 0.01f
#define KT 64
#define NTHREADS 512
#define GRID 128
#define SPLIT 4          // K splits of the per-iter gemm
#define NCT 32           // coltiles (64 realified cols each)
#define KX 2048          // X k-dim (realified n-space)
#define CG 2048          // G cols (realified n-space)
#define KMID 1024        // realified mid (m) space

#define BUF_BYTES 24576  // per stage: A 16K | B 8K
#define SMEM_TOTAL (2 * BUF_BYTES)

// ---------------- device globals ----------------
__device__ __half g_Wb[(size_t)CG * KMID];    // r(Wb^T): [2c2+ro][2j+ri]  4MB
__device__ __half g_WfT[(size_t)KX * KMID];   // r(Wf^T) k-major: [2c1+ri][2j+b] 4MB
__device__ __half g_Wc[(size_t)CG * KX];      // [colP=2c2+ro][kP=2c1+ri]  8MB
__device__ __half g_X[2][128 * KX];           // realified x, parity buffered
__device__ __half g_yh[128 * KMID];           // realified y, fp16 (for Yb build)
__device__ float g_xs[BDIM * NDIM * 8];       // blade state (CTA-private)
__device__ float g_yr[128 * KMID];            // realified y fp32
__device__ float g_Yb[128 * CG];              // Y·Wb (constant) fp32
__device__ float g_pg[2][(size_t)SPLIT * 128 * CG];   // G split partials 2x4MB
__device__ unsigned g_fg[NCT * 32];           // gemm done per coltile
__device__ unsigned g_fu[NCT * 32];           // upd done per coltile

// ---------------- helpers ----------------
__device__ __forceinline__ uint32_t smem_u32(const void* p) {
    uint32_t a;
    asm("{ .reg .u64 t; cvta.to.shared.u64 t, %1; cvt.u32.u64 %0, t; }" : "=r"(a) : "l"(p));
    return a;
}

#define CP_ASYNC16(smem, gptr) \
    asm volatile("cp.async.cg.shared.global [%0], [%1], 16;" :: "r"(smem), "l"(gptr))
#define CP_COMMIT() asm volatile("cp.async.commit_group;" ::: "memory")
#define CP_WAIT1()  asm volatile("cp.async.wait_group 1;" ::: "memory")
#define CP_WAIT0()  asm volatile("cp.async.wait_group 0;" ::: "memory")

__device__ __forceinline__ void ldsm4(uint32_t* r, uint32_t addr) {
    asm volatile("ldmatrix.sync.aligned.m8n8.x4.shared.b16 {%0,%1,%2,%3}, [%4];"
                 : "=r"(r[0]), "=r"(r[1]), "=r"(r[2]), "=r"(r[3]) : "r"(addr));
}

__device__ __forceinline__ void mma_fp16(float* c, const uint32_t* a, uint32_t b0, uint32_t b1) {
    asm volatile(
        "mma.sync.aligned.m16n8k16.row.col.f32.f16.f16.f32 "
        "{%0,%1,%2,%3}, {%4,%5,%6,%7}, {%8,%9}, {%0,%1,%2,%3};"
        : "+f"(c[0]), "+f"(c[1]), "+f"(c[2]), "+f"(c[3])
        : "r"(a[0]), "r"(a[1]), "r"(a[2]), "r"(a[3]), "r"(b0), "r"(b1));
}

// M(v)[q][p] for blade vector v[8]  (blades [1,e1,e2,e12,e3,e13,e23,e123])
__device__ __forceinline__ void pauli_entry(const float* v, int q, int p,
                                            float* re, float* im) {
    if (q == 0) {
        if (p == 0) { *re = v[0] + v[4]; *im = v[3] + v[7]; }
        else        { *re = v[1] - v[5]; *im = -v[2] + v[6]; }
    } else {
        if (p == 0) { *re = v[1] + v[5]; *im = v[2] + v[6]; }
        else        { *re = v[0] - v[4]; *im = -v[3] + v[7]; }
    }
}

__device__ __forceinline__ void flag_wait(const unsigned* f, unsigned tgt) {
    unsigned v;
    do {
        asm volatile("ld.volatile.global.u32 %0, [%1];" : "=r"(v) : "l"(f));
    } while ((int)(v - tgt) < 0);
}

// ---------------- build kernels ----------------
__global__ void build_wb(const float* __restrict__ A) {
    size_t idx = (size_t)blockIdx.x * blockDim.x + threadIdx.x;
    if (idx >= (size_t)CG * KMID) return;
    int col = (int)(idx >> 10), k = (int)(idx & (KMID - 1));
    int n = col >> 2, qp = (col >> 1) & 1, ro = col & 1;
    int m = k >> 2, p = (k >> 1) & 1, ri = k & 1;
    const float* a = A + ((size_t)m * NDIM + n) * 8;
    float re, im;
    pauli_entry(a, qp, p, &re, &im);
    float v = (ri == 0) ? (ro == 0 ? re : -im) : (ro == 0 ? im : re);
    g_Wb[idx] = __float2half(v);
}

__global__ void build_wfT(const float* __restrict__ A) {
    size_t idx = (size_t)blockIdx.x * blockDim.x + threadIdx.x;
    if (idx >= (size_t)KX * KMID) return;
    int col = (int)(idx >> 10), k = (int)(idx & (KMID - 1));
    int n = col >> 2, q = (col >> 1) & 1, rc = col & 1;
    int m = k >> 2, pp = (k >> 1) & 1, b = k & 1;
    const float* a = A + ((size_t)m * NDIM + n) * 8;
    float re, im;
    pauli_entry(a, q, pp, &re, &im);
    float v = (b == 0) ? (rc == 0 ? re : -im) : (rc == 0 ? im : re);
    g_WfT[idx] = __float2half(v);
}

__global__ void build_yr(const float* __restrict__ y) {
    int idx = blockIdx.x * blockDim.x + threadIdx.x;
    if (idx >= 128 * KMID) return;
    int row = idx >> 10, col = idx & (KMID - 1);
    int b = row >> 1, p = row & 1;
    int m = col >> 2, pp = (col >> 1) & 1, ro = col & 1;
    const float* yv = y + ((size_t)b * MDIM + m) * 8;
    float re, im;
    pauli_entry(yv, p, pp, &re, &im);
    float v = ro ? im : re;
    g_yr[idx] = v;
    g_yh[idx] = __float2half(v);
}

__global__ void init_all() {
    int idx = blockIdx.x * blockDim.x + threadIdx.x;
    if (idx < BDIM * NDIM * 8) g_xs[idx] = 0.0f;
    if (idx < 128 * KX) {
        g_X[0][idx] = __float2half(0.0f);
        g_X[1][idx] = __float2half(0.0f);
    }
    if (idx < NCT * 32) { g_fg[idx] = 0u; g_fu[idx] = 0u; }
}

// ---------------- shared gemm pieces ----------------
__device__ __forceinline__ void issue_stage(
    uint32_t sb, int buf, int tid, const __half* Am, const __half* Wm,
    int Kdim, int c0, int kk)
{
    uint32_t base = sb + buf * BUF_BYTES;
#pragma unroll
    for (int r = 0; r < 3; r++) {
        int q = tid + (r << 9);                // 1536 16B chunks per stage
        const __half* gp;
        uint32_t tb;
        int row, cc;
        if (q < 1024) {                        // A: 128 rows x 8 chunks
            row = q >> 3; cc = q & 7;
            gp = Am + (size_t)row * Kdim + kk + cc * 8;
            tb = base;
        } else {                               // B: 64 rows x 8 chunks
            int q2 = q - 1024;
            row = q2 >> 3; cc = q2 & 7;
            gp = Wm + (size_t)(c0 + row) * Kdim + kk + cc * 8;
            tb = base + 16384;
        }
        uint32_t off = (uint32_t)((row << 7) | ((cc ^ (row & 7)) << 4));
        CP_ASYNC16(tb + off, gp);
    }
    CP_COMMIT();
}

__device__ __forceinline__ void gemm_loop(
    uint32_t sb, const __half* Am, const __half* Wm, int Kdim, int c0,
    int k0, int nst, int wm, int wn, int lrow, int lhalf, int lsw, int tid,
    float acc[2][2][4])
{
    issue_stage(sb, 0, tid, Am, Wm, Kdim, c0, k0);
    for (int s = 0; s < nst; s++) {
        if (s + 1 < nst) {
            issue_stage(sb, (s + 1) & 1, tid, Am, Wm, Kdim, c0, k0 + (s + 1) * KT);
            CP_WAIT1();
        } else {
            CP_COMMIT();
            CP_WAIT0();
        }
        __syncthreads();
        uint32_t bufb = sb + (s & 1) * BUF_BYTES;
#pragma unroll
        for (int kk = 0; kk < 4; kk++) {
            uint32_t ksel = (uint32_t)((((kk << 1) | lhalf) ^ lsw) << 4);
            uint32_t ah[2][4], bb[4];
#pragma unroll
            for (int am = 0; am < 2; am++) {
                uint32_t rb = (uint32_t)((wm * 32 + am * 16 + lrow) << 7) + ksel;
                ldsm4(ah[am], bufb + rb);
            }
            {
                uint32_t rb = (uint32_t)((wn * 16 + lrow) << 7) + ksel;
                ldsm4(bb, bufb + 16384u + rb);
            }
#pragma unroll
            for (int am = 0; am < 2; am++)
#pragma unroll
                for (int sel = 0; sel < 2; sel++)
                    mma_fp16(acc[am][sel], ah[am], bb[sel], bb[sel + 2]);
        }
        __syncthreads();
    }
}

// ---------------- Wc build gemm: Wc = g_Wb(2048x1024) @ g_WfT^T ----------------
__global__ __launch_bounds__(NTHREADS, 1) void build_wc() {
    extern __shared__ char smem[];
    uint32_t sb = smem_u32(smem);
    const int tid = threadIdx.x;
    const int cb = blockIdx.x;     // 32 colblocks of 64
    const int rb = blockIdx.y;     // 16 rowblocks of 128
    const int warp = tid >> 5, lane = tid & 31;
    const int wm = warp >> 2, wn = warp & 3;
    const int lrow = lane & 15, lhalf = lane >> 4, lsw = lrow & 7;

    float acc[2][2][4];
#pragma unroll
    for (int am = 0; am < 2; am++)
#pragma unroll
        for (int sel = 0; sel < 2; sel++)
#pragma unroll
            for (int v = 0; v < 4; v++) acc[am][sel][v] = 0.0f;

    const __half* Am = g_Wb + (size_t)rb * 128 * KMID;
    gemm_loop(sb, Am, g_WfT, KMID, cb * 64, 0, KMID / KT,
              wm, wn, lrow, lhalf, lsw, tid, acc);

    const int qrow = lane >> 2, qcol2 = (lane & 3) << 1;
#pragma unroll
    for (int am = 0; am < 2; am++)
#pragma unroll
        for (int sel = 0; sel < 2; sel++) {
            int row = rb * 128 + wm * 32 + am * 16 + qrow;
            int col = cb * 64 + wn * 16 + sel * 8 + qcol2;
            *reinterpret_cast<__half2*>(&g_Wc[(size_t)row * KX + col]) =
                __floats2half2_rn(acc[am][sel][0], acc[am][sel][1]);
            *reinterpret_cast<__half2*>(&g_Wc[(size_t)(row + 8) * KX + col]) =
                __floats2half2_rn(acc[am][sel][2], acc[am][sel][3]);
        }
}

// ---------------- Yb build gemm: Yb = g_yh(128x1024) @ Wb-tile ----------------
__global__ __launch_bounds__(NTHREADS, 1) void build_yb_mma() {
    extern __shared__ char smem[];
    uint32_t sb = smem_u32(smem);
    const int tid = threadIdx.x;
    const int cb = blockIdx.x;     // 32 colblocks of 64
    const int warp = tid >> 5, lane = tid & 31;
    const int wm = warp >> 2, wn = warp & 3;
    const int lrow = lane & 15, lhalf = lane >> 4, lsw = lrow & 7;

    float acc[2][2][4];
#pragma unroll
    for (int am = 0; am < 2; am++)
#pragma unroll
        for (int sel = 0; sel < 2; sel++)
#pragma unroll
            for (int v = 0; v < 4; v++) acc[am][sel][v] = 0.0f;

    gemm_loop(sb, g_yh, g_Wb, KMID, cb * 64, 0, KMID / KT,
              wm, wn, lrow, lhalf, lsw, tid, acc);

    const int qrow = lane >> 2, qcol2 = (lane & 3) << 1;
#pragma unroll
    for (int am = 0; am < 2; am++)
#pragma unroll
        for (int sel = 0; sel < 2; sel++) {
            int row = wm * 32 + am * 16 + qrow;
            int col = cb * 64 + wn * 16 + sel * 8 + qcol2;
            *reinterpret_cast<float2*>(&g_Yb[(size_t)row * CG + col]) =
                make_float2(acc[am][sel][0], acc[am][sel][1]);
            *reinterpret_cast<float2*>(&g_Yb[(size_t)(row + 8) * CG + col]) =
                make_float2(acc[am][sel][2], acc[am][sel][3]);
        }
}

// ---------------- persistent kernel (byte-identical to R13) ----------------
__global__ __launch_bounds__(NTHREADS, 1) void ista_persist(float* __restrict__ out) {
    extern __shared__ char smem[];
    uint32_t sb = smem_u32(smem);
    const int cta = blockIdx.x;
    const int t = threadIdx.x;
    const int ct = cta >> 2;       // coltile (32)
    const int ks = cta & 3;        // K split (4)
    const int warp = t >> 5, lane = t & 31;
    const int wm = warp >> 2, wn = warp & 3;
    const int lrow = lane & 15, lhalf = lane >> 4, lsw = lrow & 7;
    const int qrow = lane >> 2, qcol2 = (lane & 3) << 1;

    for (int it = 0; it < NITER; it++) {
        const int p = it & 1;

        // ---- gemm: pg[p][ks] cols [ct*64,+64) = X[p] @ Wc-tile, K slice ks ----
        {
            float acc[2][2][4];
#pragma unroll
            for (int am = 0; am < 2; am++)
#pragma unroll
                for (int sel = 0; sel < 2; sel++)
#pragma unroll
                    for (int v = 0; v < 4; v++) acc[am][sel][v] = 0.0f;

            gemm_loop(sb, g_X[p], g_Wc, KX, ct * 64, ks * 512, 512 / KT,
                      wm, wn, lrow, lhalf, lsw, t, acc);

            float* po = g_pg[p] + (size_t)ks * 128 * CG;
#pragma unroll
            for (int am = 0; am < 2; am++)
#pragma unroll
                for (int sel = 0; sel < 2; sel++) {
                    int row = wm * 32 + am * 16 + qrow;
                    int col = ct * 64 + wn * 16 + sel * 8 + qcol2;
                    *reinterpret_cast<float2*>(&po[(size_t)row * CG + col]) =
                        make_float2(acc[am][sel][0], acc[am][sel][1]);
                    *reinterpret_cast<float2*>(&po[(size_t)(row + 8) * CG + col]) =
                        make_float2(acc[am][sel][2], acc[am][sel][3]);
                }
        }
        __syncthreads();
        if (t == 0) {
            __threadfence();
            atomicAdd(&g_fg[ct * 32], 1u);
            flag_wait(&g_fg[ct * 32], 4u * (it + 1));   // 4 splits of my coltile
            __threadfence();
        }
        __syncthreads();

        // ---- upd: b in [ks*16,+16), n in [ct*16,+16); G = sum(pg) - Yb ----
        if (t < 256) {
            int b = ks * 16 + (t >> 4);
            int n = ct * 16 + (t & 15);
            size_t r0 = (size_t)(2 * b) * CG + 4 * n;
            size_t r1 = r0 + CG;
            float4 yb0 = *reinterpret_cast<const float4*>(&g_Yb[r0]);
            float4 yb1 = *reinterpret_cast<const float4*>(&g_Yb[r1]);
            float4 G0 = make_float4(-yb0.x, -yb0.y, -yb0.z, -yb0.w);
            float4 G1 = make_float4(-yb1.x, -yb1.y, -yb1.z, -yb1.w);
#pragma unroll
            for (int q = 0; q < SPLIT; q++) {
                float4 a = *reinterpret_cast<const float4*>(
                    &g_pg[p][(size_t)q * 128 * CG + r0]);
                float4 c = *reinterpret_cast<const float4*>(
                    &g_pg[p][(size_t)q * 128 * CG + r1]);
                G0.x += a.x; G0.y += a.y; G0.z += a.z; G0.w += a.w;
                G1.x += c.x; G1.y += c.y; G1.z += c.z; G1.w += c.w;
            }
            float g[8];
            g[0] = 0.5f * (G0.x + G1.z);
            g[4] = 0.5f * (G0.x - G1.z);
            g[3] = 0.5f * (G0.y - G1.w);
            g[7] = 0.5f * (G0.y + G1.w);
            g[1] = 0.5f * (G0.z + G1.x);
            g[5] = 0.5f * (G1.x - G0.z);
            g[2] = 0.5f * (G1.y - G0.w);
            g[6] = 0.5f * (G0.w + G1.y);

            int idx = b * NDIM + n;
            float* xs = g_xs + (size_t)idx * 8;
            float x[8];
#pragma unroll
            for (int i = 0; i < 8; i++) {
                float xv = xs[i] - STEPF * g[i];
                float thr = (i == 0) ? 0.0f : ((i == 7) ? 0.002f : 0.001f);
                float a = fabsf(xv) - thr;
                x[i] = (a > 0.0f) ? copysignf(a, xv) : 0.0f;
                xs[i] = x[i];
            }
            const int p1 = (it + 1) & 1;
            __half2* X0 = reinterpret_cast<__half2*>(&g_X[p1][(size_t)(2 * b) * KX + 4 * n]);
            __half2* X1 = reinterpret_cast<__half2*>(&g_X[p1][(size_t)(2 * b + 1) * KX + 4 * n]);
            X0[0] = __floats2half2_rn(x[0] + x[4], x[3] + x[7]);
            X0[1] = __floats2half2_rn(x[1] - x[5], -x[2] + x[6]);
            X1[0] = __floats2half2_rn(x[1] + x[5], x[2] + x[6]);
            X1[1] = __floats2half2_rn(x[0] - x[4], -x[3] + x[7]);

            if (it == NITER - 1) {
                float4* po = reinterpret_cast<float4*>(&out[(size_t)idx * 8]);
                po[0] = make_float4(x[0], x[1], x[2], x[3]);
                po[1] = make_float4(x[4], x[5], x[6], x[7]);
            }
        }
        __syncthreads();
        if (t == 0) {
            __threadfence();
            atomicAdd(&g_fu[ct * 32], 1u);
            if (it + 1 < NITER) {
                unsigned tgt = 4u * (it + 1);
#pragma unroll
                for (int j = 0; j < 8; j++)          // X slice producers
                    flag_wait(&g_fu[(ks * 8 + j) * 32], tgt);
                flag_wait(&g_fu[ct * 32], tgt);      // pg WAR guard (own coltile)
                __threadfence();
            }
        }
        __syncthreads();
    }
}

// ---------------- host ----------------
extern "C" void kernel_launch(void* const* d_in, const int* in_sizes, int n_in,
                              void* d_out, int out_size)
{
    const float* y = (const float*)d_in[0];
    const float* A = (const float*)d_in[1];
    if (n_in >= 2 && in_sizes[0] > in_sizes[1]) {
        const float* t = y; y = A; A = t;
    }

    cudaFuncSetAttribute(build_wc, cudaFuncAttributeMaxDynamicSharedMemorySize, SMEM_TOTAL);
    cudaFuncSetAttribute(build_yb_mma, cudaFuncAttributeMaxDynamicSharedMemorySize, SMEM_TOTAL);
    cudaFuncSetAttribute(ista_persist, cudaFuncAttributeMaxDynamicSharedMemorySize, SMEM_TOTAL);

    build_wb<<<(int)(((size_t)CG * KMID + 255) / 256), 256>>>(A);
    build_wfT<<<(int)(((size_t)KX * KMID + 255) / 256), 256>>>(A);
    build_yr<<<(128 * KMID + 255) / 256, 256>>>(y);
    build_yb_mma<<<32, NTHREADS, SMEM_TOTAL>>>();
    build_wc<<<dim3(32, 16), NTHREADS, SMEM_TOTAL>>>();
    init_all<<<(128 * KX + 255) / 256, 256>>>();

    ista_persist<<<GRID, NTHREADS, SMEM_TOTAL>>>((float*)d_out);
}